// round 1
// baseline (speedup 1.0000x reference)
#include <cuda_runtime.h>
#include <math.h>

// Problem constants
#define Bb   4
#define Ss   2048
#define Dd   1024    // d_in == d_out == 1024

// GEMM tiling
#define BM 64
#define BN 64
#define BK 16

// Scratch for Q, K, V projections (device globals: allocation-free rule)
static __device__ float g_Q[(size_t)Bb * Ss * Dd];
static __device__ float g_K[(size_t)Bb * Ss * Dd];
static __device__ float g_V[(size_t)Bb * Ss * Dd];

// ---------------------------------------------------------------------------
// Kernel 1: QKV projection.  C[8192,1024] = x[8192,1024] @ W[1024,1024]
// blockIdx.z selects (Wq->Q, Wk->K, Wv->V).
// ---------------------------------------------------------------------------
__global__ __launch_bounds__(256) void qkv_kernel(
    const float* __restrict__ x,
    const float* __restrict__ Wq,
    const float* __restrict__ Wk,
    const float* __restrict__ Wv)
{
    __shared__ float As[BM][BK + 1];   // padded: conflict-free column reads
    __shared__ float Bs[BK][BN];       // row-major: float4 fragment reads

    const float* W   = (blockIdx.z == 0) ? Wq : (blockIdx.z == 1) ? Wk : Wv;
    float*       out = (blockIdx.z == 0) ? g_Q : (blockIdx.z == 1) ? g_K : g_V;

    const int K = Dd, N = Dd;
    const int rowBase = blockIdx.y * BM;
    const int colBase = blockIdx.x * BN;
    const int tid = threadIdx.x;
    const int tx = tid & 15, ty = tid >> 4;

    float acc[4][4] = {};

    for (int k0 = 0; k0 < K; k0 += BK) {
        #pragma unroll
        for (int i = tid; i < BM * BK; i += 256) {
            int r = i / BK, c = i % BK;
            As[r][c] = x[(size_t)(rowBase + r) * K + k0 + c];
        }
        #pragma unroll
        for (int i = tid; i < BK * BN; i += 256) {
            int r = i / BN, c = i % BN;
            Bs[r][c] = W[(size_t)(k0 + r) * N + colBase + c];
        }
        __syncthreads();
        #pragma unroll
        for (int kk = 0; kk < BK; kk++) {
            float a[4];
            #pragma unroll
            for (int m = 0; m < 4; m++) a[m] = As[ty * 4 + m][kk];
            float4 b4 = *(const float4*)&Bs[kk][tx * 4];
            float bb[4] = {b4.x, b4.y, b4.z, b4.w};
            #pragma unroll
            for (int m = 0; m < 4; m++)
                #pragma unroll
                for (int n = 0; n < 4; n++)
                    acc[m][n] += a[m] * bb[n];
        }
        __syncthreads();
    }

    #pragma unroll
    for (int m = 0; m < 4; m++) {
        float4 v = make_float4(acc[m][0], acc[m][1], acc[m][2], acc[m][3]);
        *(float4*)&out[(size_t)(rowBase + ty * 4 + m) * N + colBase + tx * 4] = v;
    }
}

// ---------------------------------------------------------------------------
// Kernel 2: raw scores = Q @ K^T per batch, causal tile skip.
// Writes raw (unscaled, unmasked) scores into the att_weights output region.
// Tiles fully above the diagonal are skipped (softmax writes zeros there).
// ---------------------------------------------------------------------------
__global__ __launch_bounds__(256) void scores_kernel(float* __restrict__ wts)
{
    const int b = blockIdx.z;
    const int rowBase = blockIdx.y * BM;   // query index i
    const int colBase = blockIdx.x * BN;   // key index j
    if (colBase > rowBase + BM - 1) return;  // fully masked tile

    const float* Q = g_Q + (size_t)b * Ss * Dd;
    const float* Kp = g_K + (size_t)b * Ss * Dd;
    float* C = wts + (size_t)b * Ss * Ss;

    __shared__ float As[BM][BK + 1];
    __shared__ float Bs[BN][BK + 1];

    const int tid = threadIdx.x;
    const int tx = tid & 15, ty = tid >> 4;

    float acc[4][4] = {};

    for (int k0 = 0; k0 < Dd; k0 += BK) {
        #pragma unroll
        for (int i = tid; i < BM * BK; i += 256) {
            int r = i / BK, c = i % BK;
            As[r][c] = Q[(size_t)(rowBase + r) * Dd + k0 + c];
        }
        #pragma unroll
        for (int i = tid; i < BN * BK; i += 256) {
            int r = i / BK, c = i % BK;
            Bs[r][c] = Kp[(size_t)(colBase + r) * Dd + k0 + c];
        }
        __syncthreads();
        #pragma unroll
        for (int kk = 0; kk < BK; kk++) {
            float a[4], bb[4];
            #pragma unroll
            for (int m = 0; m < 4; m++) a[m] = As[ty * 4 + m][kk];
            #pragma unroll
            for (int n = 0; n < 4; n++) bb[n] = Bs[tx * 4 + n][kk];
            #pragma unroll
            for (int m = 0; m < 4; m++)
                #pragma unroll
                for (int n = 0; n < 4; n++)
                    acc[m][n] += a[m] * bb[n];
        }
        __syncthreads();
    }

    #pragma unroll
    for (int m = 0; m < 4; m++) {
        float4 v = make_float4(acc[m][0], acc[m][1], acc[m][2], acc[m][3]);
        *(float4*)&C[(size_t)(rowBase + ty * 4 + m) * Ss + colBase + tx * 4] = v;
    }
}

// ---------------------------------------------------------------------------
// Kernel 3: causal softmax in-place on the weights buffer.
// One block per (batch, query row). Row cached in smem. Zeros above diagonal.
// ---------------------------------------------------------------------------
__global__ __launch_bounds__(256) void softmax_kernel(float* __restrict__ wts)
{
    const int b = blockIdx.y;
    const int i = blockIdx.x;
    float* row = wts + ((size_t)b * Ss + i) * Ss;
    const int n = i + 1;                       // valid keys: j <= i
    const float scale = 0.03125f;              // 1/sqrt(1024)

    __shared__ float srow[Ss];
    __shared__ float red[8];
    const int tid = threadIdx.x;
    const int lane = tid & 31, warp = tid >> 5;

    // pass 1: load+scale, local max
    float mx = -INFINITY;
    for (int j = tid; j < n; j += 256) {
        float v = row[j] * scale;
        srow[j] = v;
        mx = fmaxf(mx, v);
    }
    #pragma unroll
    for (int o = 16; o; o >>= 1) mx = fmaxf(mx, __shfl_xor_sync(~0u, mx, o));
    if (lane == 0) red[warp] = mx;
    __syncthreads();
    float bmax = -INFINITY;
    #pragma unroll
    for (int w = 0; w < 8; w++) bmax = fmaxf(bmax, red[w]);
    __syncthreads();

    // pass 2: exp + sum
    float sum = 0.0f;
    for (int j = tid; j < n; j += 256) {
        float e = expf(srow[j] - bmax);
        srow[j] = e;
        sum += e;
    }
    #pragma unroll
    for (int o = 16; o; o >>= 1) sum += __shfl_xor_sync(~0u, sum, o);
    if (lane == 0) red[warp] = sum;
    __syncthreads();
    float bsum = 0.0f;
    #pragma unroll
    for (int w = 0; w < 8; w++) bsum += red[w];
    const float inv = 1.0f / bsum;

    // pass 3: normalize + write (exact zeros above the diagonal)
    for (int j = tid; j < Ss; j += 256)
        row[j] = (j < n) ? srow[j] * inv : 0.0f;
}

// ---------------------------------------------------------------------------
// Kernel 4: att_output = weights @ V per batch, K-loop truncated by causality.
// ---------------------------------------------------------------------------
__global__ __launch_bounds__(256) void av_kernel(
    const float* __restrict__ wts, float* __restrict__ out)
{
    const int b = blockIdx.z;
    const int rowBase = blockIdx.y * BM;
    const int colBase = blockIdx.x * BN;

    const float* W = wts + (size_t)b * Ss * Ss;
    const float* V = g_V + (size_t)b * Ss * Dd;
    float* C = out + (size_t)b * Ss * Dd;

    __shared__ float As[BM][BK + 1];
    __shared__ float Bs[BK][BN];

    const int tid = threadIdx.x;
    const int tx = tid & 15, ty = tid >> 4;

    float acc[4][4] = {};
    const int kMax = rowBase + BM;   // weights are 0 for j > i; max i = rowBase+63

    for (int k0 = 0; k0 < kMax; k0 += BK) {
        #pragma unroll
        for (int i = tid; i < BM * BK; i += 256) {
            int r = i / BK, c = i % BK;
            As[r][c] = W[(size_t)(rowBase + r) * Ss + k0 + c];
        }
        #pragma unroll
        for (int i = tid; i < BK * BN; i += 256) {
            int r = i / BN, c = i % BN;
            Bs[r][c] = V[(size_t)(k0 + r) * Dd + colBase + c];
        }
        __syncthreads();
        #pragma unroll
        for (int kk = 0; kk < BK; kk++) {
            float a[4];
            #pragma unroll
            for (int m = 0; m < 4; m++) a[m] = As[ty * 4 + m][kk];
            float4 b4 = *(const float4*)&Bs[kk][tx * 4];
            float bb[4] = {b4.x, b4.y, b4.z, b4.w};
            #pragma unroll
            for (int m = 0; m < 4; m++)
                #pragma unroll
                for (int n = 0; n < 4; n++)
                    acc[m][n] += a[m] * bb[n];
        }
        __syncthreads();
    }

    #pragma unroll
    for (int m = 0; m < 4; m++) {
        float4 v = make_float4(acc[m][0], acc[m][1], acc[m][2], acc[m][3]);
        *(float4*)&C[(size_t)(rowBase + ty * 4 + m) * Dd + colBase + tx * 4] = v;
    }
}

// ---------------------------------------------------------------------------
extern "C" void kernel_launch(void* const* d_in, const int* in_sizes, int n_in,
                              void* d_out, int out_size)
{
    const float* x  = (const float*)d_in[0];
    const float* Wq = (const float*)d_in[1];
    const float* Wk = (const float*)d_in[2];
    const float* Wv = (const float*)d_in[3];

    float* out = (float*)d_out;                          // att_output [4,2048,1024]
    float* wts = out + (size_t)Bb * Ss * Dd;             // att_weights [4,2048,2048]

    // 1) Q/K/V projections: [8192,1024] @ [1024,1024], z selects weight
    qkv_kernel<<<dim3(Dd / BN, (Bb * Ss) / BM, 3), 256>>>(x, Wq, Wk, Wv);

    // 2) raw scores (causal tiles only) into weights buffer
    scores_kernel<<<dim3(Ss / BN, Ss / BM, Bb), 256>>>(wts);

    // 3) in-place causal softmax
    softmax_kernel<<<dim3(Ss, Bb), 256>>>(wts);

    // 4) att_output = weights @ V (causal-truncated K loop)
    av_kernel<<<dim3(Dd / BN, Ss / BM, Bb), 256>>>(wts, out);
}

// round 5
// speedup vs baseline: 1.8007x; 1.8007x over previous
#include <cuda_runtime.h>
#include <math.h>
#include <stdint.h>

// Problem constants
#define Bb   4
#define Ss   2048
#define Dd   1024

// Block tiling
#define BMT 128
#define BNT 128
#define BKT 32

// Scratch for Q, K, V (device globals: allocation-free rule)
static __device__ float g_Q[(size_t)Bb * Ss * Dd];
static __device__ float g_K[(size_t)Bb * Ss * Dd];
static __device__ float g_V[(size_t)Bb * Ss * Dd];

// ---------------------------------------------------------------------------
// tf32 helpers
// ---------------------------------------------------------------------------
__device__ __forceinline__ uint32_t f2tf(float v) {
    uint32_t r;
    asm("cvt.rna.tf32.f32 %0, %1;" : "=r"(r) : "f"(v));
    return r;
}

__device__ __forceinline__ void split_tf32(float v, uint32_t& hi, uint32_t& lo) {
    hi = f2tf(v);
    lo = f2tf(v - __uint_as_float(hi));
}

__device__ __forceinline__ void mma_tf32(float* d, const uint32_t* a, const uint32_t* b) {
    asm volatile(
        "mma.sync.aligned.m16n8k8.row.col.f32.tf32.tf32.f32 "
        "{%0,%1,%2,%3}, {%4,%5,%6,%7}, {%8,%9}, {%0,%1,%2,%3};"
        : "+f"(d[0]), "+f"(d[1]), "+f"(d[2]), "+f"(d[3])
        : "r"(a[0]), "r"(a[1]), "r"(a[2]), "r"(a[3]), "r"(b[0]), "r"(b[1]));
}

// Smem strides (floats): padded for 16B alignment + conflict-free fragment reads
#define LDA 36     // A tile: [128][36]  (bank = 4*row + col mod 32)
#define LDB 132    // B tile: [32][132]

// ---------------------------------------------------------------------------
// Kernel 1: QKV projection.  out[8192,1024] = x[8192,1024] @ W[1024,1024]
// blockIdx.z selects weight/output. 3xTF32 mma.
// ---------------------------------------------------------------------------
__global__ __launch_bounds__(256) void qkv_tf32_kernel(
    const float* __restrict__ x,
    const float* __restrict__ Wq,
    const float* __restrict__ Wk,
    const float* __restrict__ Wv)
{
    __shared__ float As[BMT][LDA];
    __shared__ float Bs[BKT][LDB];

    const float* W   = (blockIdx.z == 0) ? Wq : (blockIdx.z == 1) ? Wk : Wv;
    float*       out = (blockIdx.z == 0) ? g_Q : (blockIdx.z == 1) ? g_K : g_V;

    const int rowBase = blockIdx.y * BMT;
    const int colBase = blockIdx.x * BNT;
    const int tid  = threadIdx.x;
    const int warp = tid >> 5, lane = tid & 31;
    const int wm = warp & 1, wn = warp >> 1;       // 2 x 4 warp grid
    const int g = lane >> 2, r = lane & 3;

    float acc[4][4][4] = {};

    for (int k0 = 0; k0 < Dd; k0 += BKT) {
        // A tile: 128x32 (row-major, ld=Dd)
        #pragma unroll
        for (int i = 0; i < 4; i++) {
            int idx = tid + i * 256;
            int row = idx >> 3, c4 = (idx & 7) * 4;
            float4 v = *(const float4*)&x[(size_t)(rowBase + row) * Dd + k0 + c4];
            As[row][c4] = v.x; As[row][c4+1] = v.y; As[row][c4+2] = v.z; As[row][c4+3] = v.w;
        }
        // B tile: 32x128 (row-major, ld=Dd)
        #pragma unroll
        for (int i = 0; i < 4; i++) {
            int idx = tid + i * 256;
            int row = idx >> 5, c4 = (idx & 31) * 4;
            *(float4*)&Bs[row][c4] = *(const float4*)&W[(size_t)(k0 + row) * Dd + colBase + c4];
        }
        __syncthreads();

        #pragma unroll
        for (int ks = 0; ks < 4; ks++) {
            const int kk = ks * 8;
            uint32_t ahi[4][4], alo[4][4];
            #pragma unroll
            for (int t = 0; t < 4; t++) {
                int row0 = wm * 64 + t * 16 + g;
                split_tf32(As[row0    ][kk + r    ], ahi[t][0], alo[t][0]);
                split_tf32(As[row0 + 8][kk + r    ], ahi[t][1], alo[t][1]);
                split_tf32(As[row0    ][kk + r + 4], ahi[t][2], alo[t][2]);
                split_tf32(As[row0 + 8][kk + r + 4], ahi[t][3], alo[t][3]);
            }
            uint32_t bhi[4][2], blo[4][2];
            #pragma unroll
            for (int u = 0; u < 4; u++) {
                int n = wn * 32 + u * 8 + g;
                split_tf32(Bs[kk + r    ][n], bhi[u][0], blo[u][0]);
                split_tf32(Bs[kk + r + 4][n], bhi[u][1], blo[u][1]);
            }
            #pragma unroll
            for (int t = 0; t < 4; t++)
                #pragma unroll
                for (int u = 0; u < 4; u++) {
                    mma_tf32(acc[t][u], ahi[t], bhi[u]);
                    mma_tf32(acc[t][u], ahi[t], blo[u]);
                    mma_tf32(acc[t][u], alo[t], bhi[u]);
                }
        }
        __syncthreads();
    }

    #pragma unroll
    for (int t = 0; t < 4; t++)
        #pragma unroll
        for (int u = 0; u < 4; u++) {
            int row0 = rowBase + wm * 64 + t * 16 + g;
            int col  = colBase + wn * 32 + u * 8 + 2 * r;
            *(float2*)&out[(size_t)row0 * Dd + col]       = make_float2(acc[t][u][0], acc[t][u][1]);
            *(float2*)&out[(size_t)(row0 + 8) * Dd + col] = make_float2(acc[t][u][2], acc[t][u][3]);
        }
}

// ---------------------------------------------------------------------------
// Kernel 2: raw scores = Q @ K^T per batch, causal tile skip. 3xTF32 mma.
// K is kept row-major [n][k] in smem; B fragment indexed as Ks[n][k].
// ---------------------------------------------------------------------------
__global__ __launch_bounds__(256) void scores_tf32_kernel(float* __restrict__ wts)
{
    const int b = blockIdx.z;
    const int rowBase = blockIdx.y * BMT;    // query i
    const int colBase = blockIdx.x * BNT;    // key j
    if (colBase > rowBase + BMT - 1) return; // fully masked tile

    const float* Q  = g_Q + (size_t)b * Ss * Dd;
    const float* Kp = g_K + (size_t)b * Ss * Dd;
    float* C = wts + (size_t)b * Ss * Ss;

    __shared__ float As[BMT][LDA];
    __shared__ float Ks[BNT][LDA];

    const int tid  = threadIdx.x;
    const int warp = tid >> 5, lane = tid & 31;
    const int wm = warp & 1, wn = warp >> 1;
    const int g = lane >> 2, r = lane & 3;

    float acc[4][4][4] = {};

    for (int k0 = 0; k0 < Dd; k0 += BKT) {
        #pragma unroll
        for (int i = 0; i < 4; i++) {
            int idx = tid + i * 256;
            int row = idx >> 3, c4 = (idx & 7) * 4;
            float4 v = *(const float4*)&Q[(size_t)(rowBase + row) * Dd + k0 + c4];
            As[row][c4] = v.x; As[row][c4+1] = v.y; As[row][c4+2] = v.z; As[row][c4+3] = v.w;
            float4 w = *(const float4*)&Kp[(size_t)(colBase + row) * Dd + k0 + c4];
            Ks[row][c4] = w.x; Ks[row][c4+1] = w.y; Ks[row][c4+2] = w.z; Ks[row][c4+3] = w.w;
        }
        __syncthreads();

        #pragma unroll
        for (int ks = 0; ks < 4; ks++) {
            const int kk = ks * 8;
            uint32_t ahi[4][4], alo[4][4];
            #pragma unroll
            for (int t = 0; t < 4; t++) {
                int row0 = wm * 64 + t * 16 + g;
                split_tf32(As[row0    ][kk + r    ], ahi[t][0], alo[t][0]);
                split_tf32(As[row0 + 8][kk + r    ], ahi[t][1], alo[t][1]);
                split_tf32(As[row0    ][kk + r + 4], ahi[t][2], alo[t][2]);
                split_tf32(As[row0 + 8][kk + r + 4], ahi[t][3], alo[t][3]);
            }
            uint32_t bhi[4][2], blo[4][2];
            #pragma unroll
            for (int u = 0; u < 4; u++) {
                int n = wn * 32 + u * 8 + g;
                split_tf32(Ks[n][kk + r    ], bhi[u][0], blo[u][0]);
                split_tf32(Ks[n][kk + r + 4], bhi[u][1], blo[u][1]);
            }
            #pragma unroll
            for (int t = 0; t < 4; t++)
                #pragma unroll
                for (int u = 0; u < 4; u++) {
                    mma_tf32(acc[t][u], ahi[t], bhi[u]);
                    mma_tf32(acc[t][u], ahi[t], blo[u]);
                    mma_tf32(acc[t][u], alo[t], bhi[u]);
                }
        }
        __syncthreads();
    }

    #pragma unroll
    for (int t = 0; t < 4; t++)
        #pragma unroll
        for (int u = 0; u < 4; u++) {
            int row0 = rowBase + wm * 64 + t * 16 + g;
            int col  = colBase + wn * 32 + u * 8 + 2 * r;
            *(float2*)&C[(size_t)row0 * Ss + col]       = make_float2(acc[t][u][0], acc[t][u][1]);
            *(float2*)&C[(size_t)(row0 + 8) * Ss + col] = make_float2(acc[t][u][2], acc[t][u][3]);
        }
}

// ---------------------------------------------------------------------------
// Kernel 3: causal softmax in-place (unchanged from R1).
// ---------------------------------------------------------------------------
__global__ __launch_bounds__(256) void softmax_kernel(float* __restrict__ wts)
{
    const int b = blockIdx.y;
    const int i = blockIdx.x;
    float* row = wts + ((size_t)b * Ss + i) * Ss;
    const int n = i + 1;
    const float scale = 0.03125f;   // 1/sqrt(1024)

    __shared__ float srow[Ss];
    __shared__ float red[8];
    const int tid = threadIdx.x;
    const int lane = tid & 31, warp = tid >> 5;

    float mx = -INFINITY;
    for (int j = tid; j < n; j += 256) {
        float v = row[j] * scale;
        srow[j] = v;
        mx = fmaxf(mx, v);
    }
    #pragma unroll
    for (int o = 16; o; o >>= 1) mx = fmaxf(mx, __shfl_xor_sync(~0u, mx, o));
    if (lane == 0) red[warp] = mx;
    __syncthreads();
    float bmax = -INFINITY;
    #pragma unroll
    for (int w = 0; w < 8; w++) bmax = fmaxf(bmax, red[w]);
    __syncthreads();

    float sum = 0.0f;
    for (int j = tid; j < n; j += 256) {
        float e = expf(srow[j] - bmax);
        srow[j] = e;
        sum += e;
    }
    #pragma unroll
    for (int o = 16; o; o >>= 1) sum += __shfl_xor_sync(~0u, sum, o);
    if (lane == 0) red[warp] = sum;
    __syncthreads();
    float bsum = 0.0f;
    #pragma unroll
    for (int w = 0; w < 8; w++) bsum += red[w];
    const float inv = 1.0f / bsum;

    for (int j = tid; j < Ss; j += 256)
        row[j] = (j < n) ? srow[j] * inv : 0.0f;
}

// ---------------------------------------------------------------------------
// Kernel 4: att_output = weights @ V per batch, causal K truncation. 3xTF32.
// ---------------------------------------------------------------------------
__global__ __launch_bounds__(256) void av_tf32_kernel(
    const float* __restrict__ wts, float* __restrict__ out)
{
    const int b = blockIdx.z;
    const int rowBase = blockIdx.y * BMT;
    const int colBase = blockIdx.x * BNT;

    const float* Wm = wts + (size_t)b * Ss * Ss;
    const float* V  = g_V + (size_t)b * Ss * Dd;
    float* C = out + (size_t)b * Ss * Dd;

    __shared__ float As[BMT][LDA];
    __shared__ float Bs[BKT][LDB];

    const int tid  = threadIdx.x;
    const int warp = tid >> 5, lane = tid & 31;
    const int wm = warp & 1, wn = warp >> 1;
    const int g = lane >> 2, r = lane & 3;

    float acc[4][4][4] = {};
    const int kMax = rowBase + BMT;   // weights zero for j > i

    for (int k0 = 0; k0 < kMax; k0 += BKT) {
        #pragma unroll
        for (int i = 0; i < 4; i++) {
            int idx = tid + i * 256;
            int row = idx >> 3, c4 = (idx & 7) * 4;
            float4 v = *(const float4*)&Wm[(size_t)(rowBase + row) * Ss + k0 + c4];
            As[row][c4] = v.x; As[row][c4+1] = v.y; As[row][c4+2] = v.z; As[row][c4+3] = v.w;
        }
        #pragma unroll
        for (int i = 0; i < 4; i++) {
            int idx = tid + i * 256;
            int row = idx >> 5, c4 = (idx & 31) * 4;
            *(float4*)&Bs[row][c4] = *(const float4*)&V[(size_t)(k0 + row) * Dd + colBase + c4];
        }
        __syncthreads();

        #pragma unroll
        for (int ks = 0; ks < 4; ks++) {
            const int kk = ks * 8;
            uint32_t ahi[4][4], alo[4][4];
            #pragma unroll
            for (int t = 0; t < 4; t++) {
                int row0 = wm * 64 + t * 16 + g;
                split_tf32(As[row0    ][kk + r    ], ahi[t][0], alo[t][0]);
                split_tf32(As[row0 + 8][kk + r    ], ahi[t][1], alo[t][1]);
                split_tf32(As[row0    ][kk + r + 4], ahi[t][2], alo[t][2]);
                split_tf32(As[row0 + 8][kk + r + 4], ahi[t][3], alo[t][3]);
            }
            uint32_t bhi[4][2], blo[4][2];
            #pragma unroll
            for (int u = 0; u < 4; u++) {
                int n = wn * 32 + u * 8 + g;
                split_tf32(Bs[kk + r    ][n], bhi[u][0], blo[u][0]);
                split_tf32(Bs[kk + r + 4][n], bhi[u][1], blo[u][1]);
            }
            #pragma unroll
            for (int t = 0; t < 4; t++)
                #pragma unroll
                for (int u = 0; u < 4; u++) {
                    mma_tf32(acc[t][u], ahi[t], bhi[u]);
                    mma_tf32(acc[t][u], ahi[t], blo[u]);
                    mma_tf32(acc[t][u], alo[t], bhi[u]);
                }
        }
        __syncthreads();
    }

    #pragma unroll
    for (int t = 0; t < 4; t++)
        #pragma unroll
        for (int u = 0; u < 4; u++) {
            int row0 = rowBase + wm * 64 + t * 16 + g;
            int col  = colBase + wn * 32 + u * 8 + 2 * r;
            *(float2*)&C[(size_t)row0 * Dd + col]       = make_float2(acc[t][u][0], acc[t][u][1]);
            *(float2*)&C[(size_t)(row0 + 8) * Dd + col] = make_float2(acc[t][u][2], acc[t][u][3]);
        }
}

// ---------------------------------------------------------------------------
extern "C" void kernel_launch(void* const* d_in, const int* in_sizes, int n_in,
                              void* d_out, int out_size)
{
    const float* x  = (const float*)d_in[0];
    const float* Wq = (const float*)d_in[1];
    const float* Wk = (const float*)d_in[2];
    const float* Wv = (const float*)d_in[3];

    float* out = (float*)d_out;                  // att_output [4,2048,1024]
    float* wts = out + (size_t)Bb * Ss * Dd;     // att_weights [4,2048,2048]

    qkv_tf32_kernel<<<dim3(Dd / BNT, (Bb * Ss) / BMT, 3), 256>>>(x, Wq, Wk, Wv);
    scores_tf32_kernel<<<dim3(Ss / BNT, Ss / BMT, Bb), 256>>>(wts);
    softmax_kernel<<<dim3(Ss, Bb), 256>>>(wts);
    av_tf32_kernel<<<dim3(Dd / BNT, Ss / BMT, Bb), 256>>>(wts, out);
}